// round 14
// baseline (speedup 1.0000x reference)
#include <cuda_runtime.h>
#include <cstdint>

#define BATCH 4
#define NPTS  8192
#define GDIM  64                  // grid cells per axis
#define NCELL (GDIM * GDIM)       // 4096
#define CAP   20                  // max pts/cell (lambda=2; P(overflow)~1e-14)
#define HCELL (1.0f / GDIM)
#define NTAB  (2 * BATCH)         // set s (0=pred,1=gt) x batch
#define NQ    (2 * BATCH * NPTS)  // 65536 points == queries
#define NTHR  256
#define TPQ   4                   // threads per query
#define NSB   (TPQ * NQ / NTHR)   // 1024 search blocks

// Persistent scratch (zero at load; search's last block re-zeros counts).
// g_cell slots beyond a cell's count hold stale-but-finite data; the search
// predicates on count, so stale content is never observable.
__device__ int      g_ccnt[NTAB * NCELL];
__device__ float2   g_cell[NTAB * NCELL * CAP];    // 5.2 MB (L2-resident)
__device__ float    g_part[NSB];
__device__ unsigned g_done;

// ============================================================================
// K1: bin all points (atomicAdd slot; drop on overflow - P~0)
// ============================================================================
__global__ __launch_bounds__(NTHR) void k_fill(const float2* __restrict__ pred,
                                               const float2* __restrict__ gt) {
    int gid = blockIdx.x * NTHR + threadIdx.x;         // 0..65535
    int s = gid >> 15, b = (gid >> 13) & 3, i = gid & (NPTS - 1);
    const float2* src = s ? gt : pred;
    float2 p = src[b * NPTS + i];
    int cx = min(GDIM - 1, max(0, (int)(p.x * (float)GDIM)));
    int cy = min(GDIM - 1, max(0, (int)(p.y * (float)GDIM)));
    int cell = (s * BATCH + b) * NCELL + cy * GDIM + cx;
    int pos = atomicAdd(&g_ccnt[cell], 1);
    if (pos < CAP) g_cell[cell * CAP + pos] = p;
}

__device__ __forceinline__ void scan_cell(const int* __restrict__ cnts,
                                          const float2* __restrict__ cells,
                                          int c, float qx, float qy, float& best) {
    int n = min(cnts[c], CAP);
    const float2* p = &cells[(size_t)c * CAP];
    for (int j = 0; j < n; j++) {
        float2 t = p[j];
        float dx = qx - t.x, dy = qy - t.y;
        best = fminf(best, fmaf(dx, dx, dy * dy));
    }
}

// ============================================================================
// K2: exact NN, FOUR threads per query (adjacent lanes; sub = tgid&3).
// 3x3 neighborhood split 3/2/2/2. Per assigned cell, the count and the first
// 4 point slots are loaded UNCONDITIONALLY (addresses independent of count)
// -> all LDGs front-batch (MLP ~9/thread, one L2 round-trip); validity is
// applied by predication (j<n ? d : INF), so stale slot data is harmless.
// Tail loop only for cells with n>4 (Poisson lam=2 -> ~5%).
// Combine pair via shfl_xor(1), shfl_xor(2). Stragglers (best > H^2 after
// 3x3; P~0.2%): sub==0 runs expanding Chebyshev rings (ring-k cells are
// >= (k-1)*H away -> exact termination). Deterministic: min/termination
// depend only on candidate sets; final sums are fixed-order trees.
// ============================================================================
__global__ __launch_bounds__(NTHR) void k_search(const float2* __restrict__ pred,
                                                 const float2* __restrict__ gt,
                                                 float* __restrict__ out) {
    const int t = threadIdx.x, bid = blockIdx.x;
    const int tgid = bid * NTHR + t;                   // 0..262143
    const int gid = tgid >> 2, sub = tgid & 3;         // query id, sub id
    const int s = gid >> 15, b = (gid >> 13) & 3, i = gid & (NPTS - 1);

    const float2* qsrc = s ? gt : pred;
    const float2 q = qsrc[b * NPTS + i];
    const int o = s ^ 1;                               // search the OTHER set
    const int*    cnts  = &g_ccnt[(o * BATCH + b) * NCELL];
    const float2* cells = &g_cell[(size_t)(o * BATCH + b) * NCELL * CAP];

    const int cx = min(GDIM - 1, max(0, (int)(q.x * (float)GDIM)));
    const int cy = min(GDIM - 1, max(0, (int)(q.y * (float)GDIM)));

    float best = 3.4e38f;
    {
        // 3x3 cell ids (clamped; duplicates OK - min is idempotent)
        int xm = max(cx - 1, 0), xp = min(cx + 1, GDIM - 1);
        int ym = max(cy - 1, 0), yp = min(cy + 1, GDIM - 1);
        int cid9[9];
        cid9[0] = ym * GDIM + xm; cid9[1] = ym * GDIM + cx; cid9[2] = ym * GDIM + xp;
        cid9[3] = cy * GDIM + xm; cid9[4] = cy * GDIM + cx; cid9[5] = cy * GDIM + xp;
        cid9[6] = yp * GDIM + xm; cid9[7] = yp * GDIM + cx; cid9[8] = yp * GDIM + xp;

        // sub 0 -> cells {0,1,2}; sub 1 -> {3,4}; sub 2 -> {5,6}; sub 3 -> {7,8}
        const int base = (sub == 0) ? 0 : (2 * sub + 1);
        const int nc   = (sub == 0) ? 3 : 2;
        int   myid[3], myn[3];
        float4 pA[3], pB[3];
        #pragma unroll
        for (int j = 0; j < 3; j++) myid[j] = cid9[base + ((j < nc) ? j : 0)];
        // Front-batched independent loads: counts + first 4 slots per cell
        #pragma unroll
        for (int j = 0; j < 3; j++) {
            myn[j] = cnts[myid[j]];
            pA[j] = *(const float4*)&cells[(size_t)myid[j] * CAP];       // slots 0,1
            pB[j] = *(const float4*)&cells[(size_t)myid[j] * CAP + 2];   // slots 2,3
        }
        #pragma unroll
        for (int j = 0; j < 3; j++) {
            if (j >= nc) break;
            int n = min(myn[j], CAP);
            float dx, dy, d;
            dx = q.x - pA[j].x; dy = q.y - pA[j].y; d = fmaf(dx, dx, dy * dy);
            best = fminf(best, (0 < n) ? d : 3.4e38f);
            dx = q.x - pA[j].z; dy = q.y - pA[j].w; d = fmaf(dx, dx, dy * dy);
            best = fminf(best, (1 < n) ? d : 3.4e38f);
            dx = q.x - pB[j].x; dy = q.y - pB[j].y; d = fmaf(dx, dx, dy * dy);
            best = fminf(best, (2 < n) ? d : 3.4e38f);
            dx = q.x - pB[j].z; dy = q.y - pB[j].w; d = fmaf(dx, dx, dy * dy);
            best = fminf(best, (3 < n) ? d : 3.4e38f);
            // Rare tail (n>4, ~5% of cells): dependent loop
            for (int u = 4; u < n; u++) {
                float2 tp = cells[(size_t)myid[j] * CAP + u];
                dx = q.x - tp.x; dy = q.y - tp.y;
                best = fminf(best, fmaf(dx, dx, dy * dy));
            }
        }
        // Combine the 4 sub-threads (lanes 4k..4k+3 adjacent in warp)
        best = fminf(best, __shfl_xor_sync(0xFFFFFFFFu, best, 1));
        best = fminf(best, __shfl_xor_sync(0xFFFFFFFFu, best, 2));
    }

    // Straggler rings on sub 0 only (P ~ 0.2%)
    if (sub == 0 && best > HCELL * HCELL) {
        #pragma unroll 1
        for (int k = 2; k < GDIM; k++) {
            float rd = (float)(k - 1) * HCELL;
            if (best <= rd * rd) break;
            int y0 = max(cy - k, 0), y1 = min(cy + k, GDIM - 1);
            int x0 = max(cx - k, 0), x1 = min(cx + k, GDIM - 1);
            for (int yy = y0; yy <= y1; yy++) {
                if (yy == cy - k || yy == cy + k) {
                    for (int xx = x0; xx <= x1; xx++)
                        scan_cell(cnts, cells, yy * GDIM + xx, q.x, q.y, best);
                } else {
                    if (cx - k >= 0)   scan_cell(cnts, cells, yy * GDIM + cx - k, q.x, q.y, best);
                    if (cx + k < GDIM) scan_cell(cnts, cells, yy * GDIM + cx + k, q.x, q.y, best);
                }
            }
        }
    }

    // ---- Block partial (each query counted once: sub 0 contributes) ----
    __shared__ float sm[NTHR];
    __shared__ unsigned lastf;
    sm[t] = (sub == 0) ? best : 0.0f;
    __syncthreads();
    for (int off = NTHR / 2; off > 0; off >>= 1) {
        if (t < off) sm[t] += sm[t + off];
        __syncthreads();
    }
    if (t == 0) {
        g_part[bid] = sm[0];
        __threadfence();
        lastf = (atomicAdd(&g_done, 1u) == NSB - 1) ? 1u : 0u;
    }
    __syncthreads();

    if (lastf) {
        __threadfence();
        float a = ((volatile float*)g_part)[t]
                + ((volatile float*)g_part)[t + NTHR]
                + ((volatile float*)g_part)[t + 2 * NTHR]
                + ((volatile float*)g_part)[t + 3 * NTHR];
        sm[t] = a;
        __syncthreads();
        for (int off = NTHR / 2; off > 0; off >>= 1) {
            if (t < off) sm[t] += sm[t + off];
            __syncthreads();
        }
        if (t == 0) {
            out[0] = sm[0] * (1.0f / (float)(BATCH * NPTS));
            g_done = 0;                           // reset for next replay
        }
        // Re-zero counts for the next replay (dead by now: all searches done)
        int4* cc = (int4*)g_ccnt;
        #pragma unroll 4
        for (int j = t; j < NTAB * NCELL / 4; j += NTHR)
            cc[j] = make_int4(0, 0, 0, 0);
    }
}

extern "C" void kernel_launch(void* const* d_in, const int* in_sizes, int n_in,
                              void* d_out, int out_size) {
    const float2* pred = (const float2*)d_in[0];
    const float2* gt   = (const float2*)d_in[1];

    k_fill<<<NQ / NTHR, NTHR>>>(pred, gt);
    k_search<<<NSB, NTHR>>>(pred, gt, (float*)d_out);
}